// round 12
// baseline (speedup 1.0000x reference)
#include <cuda_runtime.h>
#include <cstdint>

#define NNODE 4096
#define INF   256
#define OUTF  32
#define NH    8
#define NEG_SLOPE 0.2f
#define DEGCAP 240

__device__ float          g_Wh[NH * NNODE * OUTF];   // [h][n][f], 4 MB
__device__ float          g_esrc[NH * NNODE];
__device__ float          g_edst[NH * NNODE];
__device__ int            g_deg[NNODE];
__device__ unsigned short g_adjn[NNODE][DEGCAP];
__device__ int            g_kind;                    // 0 = u8, 1 = 32-bit

__device__ __forceinline__ unsigned nib4(unsigned m) {
    return (((m & 0x01010101u) * 0x01020408u) >> 24) & 0xFu;
}

// ---------------------------------------------------------------------------
// gemm: ONE fused GEMM  Wh[n, h*32+f] = sum_i x[n,i] * W[h,i,f]
// 128 blocks x 512 thr; tile 128 rows x 64 cols (2 heads); thread 4x4.
// Fused: attention-logit epilogue + adjacency dtype detect (block 0).
// ---------------------------------------------------------------------------
__global__ void __launch_bounds__(512) gemm_kernel(
    const float* __restrict__ x, const float* __restrict__ W,
    const float* __restrict__ a_src, const float* __restrict__ a_dst,
    const void* __restrict__ adjv) {
    __shared__ float shx[128][36];   // [row][k], pitch 144B (16B-aligned)
    __shared__ float shw[32][68];    // [k][col],  pitch 272B (16B-aligned)
    __shared__ int   s_flag;

    const int t  = threadIdx.x;
    const int bx = blockIdx.x;

    // --- dtype detect (block 0 only; block-uniform branch): 32 KB sample
    if (bx == 0) {
        if (t == 0) s_flag = 0;
        __syncthreads();
        unsigned f = 0;
        const uint4* s4 = (const uint4*)adjv;
#pragma unroll
        for (int q = 0; q < 4; q++) {
            uint4 v = s4[t + q * 512];
            f |= ((v.x >> 8) & 0xFFu) | ((v.y >> 8) & 0xFFu)
               | ((v.z >> 8) & 0xFFu) | ((v.w >> 8) & 0xFFu);
        }
#pragma unroll
        for (int o = 16; o; o >>= 1)
            f |= __shfl_xor_sync(0xffffffffu, f, o);
        if ((t & 31) == 0 && f) atomicOr(&s_flag, 1);
        __syncthreads();
        if (t == 0) g_kind = s_flag ? 0 : 1;
    }

    const int row0 = (bx >> 2) * 128;   // 32 row tiles
    const int hb   = (bx & 3) * 2;      // heads hb, hb+1
    const int tx   = t & 15;            // col group: cols tx*4..+3
    const int ty   = t >> 4;            // row group 0..31: rows ty*4..+3

    float acc[4][4];
#pragma unroll
    for (int r = 0; r < 4; r++)
#pragma unroll
        for (int c = 0; c < 4; c++) acc[r][c] = 0.f;

    // prefetch chunk 0
    float4 xr[2], wr;
#pragma unroll
    for (int j = 0; j < 2; j++) {
        int idx = t + 512 * j;                  // row = idx>>3, kq = idx&7
        xr[j] = *(const float4*)(x + (size_t)(row0 + (idx >> 3)) * INF + (idx & 7) * 4);
    }
    {
        int ki = t >> 4, cq = t & 15;           // 512 float4s of W
        int h  = hb + (cq >> 3);
        wr = *(const float4*)(W + ((size_t)h * INF + ki) * OUTF + (cq & 7) * 4);
    }

#pragma unroll 1
    for (int c = 0; c < INF / 32; c++) {
        // stage current chunk (float4 stores, 16B-aligned)
#pragma unroll
        for (int j = 0; j < 2; j++) {
            int idx = t + 512 * j;
            *(float4*)&shx[idx >> 3][(idx & 7) * 4] = xr[j];
        }
        *(float4*)&shw[t >> 4][(t & 15) * 4] = wr;
        __syncthreads();

        // prefetch next chunk
        if (c < INF / 32 - 1) {
            const int kk = (c + 1) * 32;
#pragma unroll
            for (int j = 0; j < 2; j++) {
                int idx = t + 512 * j;
                xr[j] = *(const float4*)(x + (size_t)(row0 + (idx >> 3)) * INF + kk + (idx & 7) * 4);
            }
            {
                int ki = t >> 4, cq = t & 15;
                int h  = hb + (cq >> 3);
                wr = *(const float4*)(W + ((size_t)h * INF + kk + ki) * OUTF + (cq & 7) * 4);
            }
        }

        // compute: per 4-k block, 4 w-vectors + 4 x-vectors -> 64 FMAs
#pragma unroll
        for (int i4 = 0; i4 < 32; i4 += 4) {
            float4 wv0 = *(const float4*)&shw[i4 + 0][tx * 4];
            float4 wv1 = *(const float4*)&shw[i4 + 1][tx * 4];
            float4 wv2 = *(const float4*)&shw[i4 + 2][tx * 4];
            float4 wv3 = *(const float4*)&shw[i4 + 3][tx * 4];
#pragma unroll
            for (int rr = 0; rr < 4; rr++) {
                float4 xq = *(const float4*)&shx[ty * 4 + rr][i4];
                acc[rr][0] = fmaf(xq.x, wv0.x, acc[rr][0]);
                acc[rr][1] = fmaf(xq.x, wv0.y, acc[rr][1]);
                acc[rr][2] = fmaf(xq.x, wv0.z, acc[rr][2]);
                acc[rr][3] = fmaf(xq.x, wv0.w, acc[rr][3]);
                acc[rr][0] = fmaf(xq.y, wv1.x, acc[rr][0]);
                acc[rr][1] = fmaf(xq.y, wv1.y, acc[rr][1]);
                acc[rr][2] = fmaf(xq.y, wv1.z, acc[rr][2]);
                acc[rr][3] = fmaf(xq.y, wv1.w, acc[rr][3]);
                acc[rr][0] = fmaf(xq.z, wv2.x, acc[rr][0]);
                acc[rr][1] = fmaf(xq.z, wv2.y, acc[rr][1]);
                acc[rr][2] = fmaf(xq.z, wv2.z, acc[rr][2]);
                acc[rr][3] = fmaf(xq.z, wv2.w, acc[rr][3]);
                acc[rr][0] = fmaf(xq.w, wv3.x, acc[rr][0]);
                acc[rr][1] = fmaf(xq.w, wv3.y, acc[rr][1]);
                acc[rr][2] = fmaf(xq.w, wv3.z, acc[rr][2]);
                acc[rr][3] = fmaf(xq.w, wv3.w, acc[rr][3]);
            }
        }
        __syncthreads();
    }

    // epilogue: store Wh + fused logits
    const int h  = hb + (tx >> 3);
    const int f0 = (tx & 7) * 4;
    float as[4], ad[4];
#pragma unroll
    for (int q = 0; q < 4; q++) {
        as[q] = a_src[h * OUTF + f0 + q];
        ad[q] = a_dst[h * OUTF + f0 + q];
    }
#pragma unroll
    for (int rr = 0; rr < 4; rr++) {
        const int n = row0 + ty * 4 + rr;
        float4 o;
        o.x = acc[rr][0]; o.y = acc[rr][1]; o.z = acc[rr][2]; o.w = acc[rr][3];
        *(float4*)(g_Wh + ((size_t)(h << 12) + n) * OUTF + f0) = o;

        float s = acc[rr][0] * as[0] + acc[rr][1] * as[1]
                + acc[rr][2] * as[2] + acc[rr][3] * as[3];
        float d = acc[rr][0] * ad[0] + acc[rr][1] * ad[1]
                + acc[rr][2] * ad[2] + acc[rr][3] * ad[3];
#pragma unroll
        for (int o2 = 1; o2 < 8; o2 <<= 1) {
            s += __shfl_xor_sync(0xffffffffu, s, o2);
            d += __shfl_xor_sync(0xffffffffu, d, o2);
        }
        if ((tx & 7) == 0) {
            g_esrc[(h << 12) + n] = s;
            g_edst[(h << 12) + n] = d;
        }
    }
}

// ---------------------------------------------------------------------------
// scan: 1024 blocks x 128 thr, warp per row, software-prefetched stream.
// Reads g_kind (written by gemm_kernel, prior launch).
// ---------------------------------------------------------------------------
__global__ void __launch_bounds__(128) scan_kernel(const void* __restrict__ adjv) {
    const int t    = threadIdx.x;
    const int lane = t & 31;
    const int w    = t >> 5;
    const int r    = blockIdx.x * 4 + w;
    const int kind = g_kind;

    int base = 0;
    if (kind == 0) {
        const uint4* rp = (const uint4*)((const unsigned char*)adjv + (size_t)r * NNODE);
        uint4 cur = rp[lane];
        for (int it = 0; it < 8; it++) {
            uint4 nxt;
            if (it < 7) nxt = rp[(it + 1) * 32 + lane];
            unsigned m16 =  nib4(__vcmpne4(cur.x, 0u))
                         | (nib4(__vcmpne4(cur.y, 0u)) << 4)
                         | (nib4(__vcmpne4(cur.z, 0u)) << 8)
                         | (nib4(__vcmpne4(cur.w, 0u)) << 12);
            const int c0 = (it << 9) + (lane << 4);
            if ((unsigned)(r - c0) < 16u) m16 |= 1u << (r - c0);

            int cnt  = __popc(m16);
            int incl = cnt;
#pragma unroll
            for (int o = 1; o < 32; o <<= 1) {
                int v = __shfl_up_sync(0xffffffffu, incl, o);
                if (lane >= o) incl += v;
            }
            int pos = base + (incl - cnt);
            int tot = __shfl_sync(0xffffffffu, incl, 31);
            while (m16) {
                int bi = __ffs(m16) - 1;
                m16 &= m16 - 1;
                if (pos < DEGCAP) g_adjn[r][pos] = (unsigned short)(c0 + bi);
                pos++;
            }
            base += tot;
            cur = nxt;
        }
    } else {
        const uint4* rp = (const uint4*)((const unsigned char*)adjv + ((size_t)r * NNODE << 2));
        uint4 cur[4];
#pragma unroll
        for (int q = 0; q < 4; q++) cur[q] = rp[lane * 4 + q];
        for (int it = 0; it < 8; it++) {
            uint4 nxt[4];
            if (it < 7) {
#pragma unroll
                for (int q = 0; q < 4; q++)
                    nxt[q] = rp[(it + 1) * 128 + lane * 4 + q];
            }
            unsigned m16 = 0;
#pragma unroll
            for (int q = 0; q < 4; q++) {
                m16 |= (unsigned)(cur[q].x != 0) << (q * 4 + 0);
                m16 |= (unsigned)(cur[q].y != 0) << (q * 4 + 1);
                m16 |= (unsigned)(cur[q].z != 0) << (q * 4 + 2);
                m16 |= (unsigned)(cur[q].w != 0) << (q * 4 + 3);
            }
            const int c0 = (it << 9) + (lane << 4);
            if ((unsigned)(r - c0) < 16u) m16 |= 1u << (r - c0);

            int cnt  = __popc(m16);
            int incl = cnt;
#pragma unroll
            for (int o = 1; o < 32; o <<= 1) {
                int v = __shfl_up_sync(0xffffffffu, incl, o);
                if (lane >= o) incl += v;
            }
            int pos = base + (incl - cnt);
            int tot = __shfl_sync(0xffffffffu, incl, 31);
            while (m16) {
                int bi = __ffs(m16) - 1;
                m16 &= m16 - 1;
                if (pos < DEGCAP) g_adjn[r][pos] = (unsigned short)(c0 + bi);
                pos++;
            }
            base += tot;
#pragma unroll
            for (int q = 0; q < 4; q++) cur[q] = nxt[q];
        }
    }
    if (lane == 31) g_deg[r] = (base > DEGCAP) ? DEGCAP : base;
}

// ---------------------------------------------------------------------------
// agg: warp per (node, head). Edge-parallel alpha (one exp per lane),
// shfl-broadcast gather. No max-subtraction (logits O(10); exp safe;
// constant cancels in normalization).
// ---------------------------------------------------------------------------
__global__ void __launch_bounds__(256) agg_kernel(
    const float* __restrict__ bias, float* __restrict__ out) {
    const int i    = blockIdx.x;
    const int t    = threadIdx.x;
    const int w    = t >> 5;
    const int lane = t & 31;

    const int    deg = g_deg[i];
    const float  es  = g_esrc[(w << 12) + i];
    const float* ed  = g_edst + (w << 12);
    const float* whb = g_Wh + (((size_t)w << 12) * OUTF) + lane;

    float acc = 0.f, ssum = 0.f;
    for (int c0 = 0; c0 < deg; c0 += 32) {
        const int k = c0 + lane;
        int   j = 0;
        float p = 0.f;
        if (k < deg) {
            j = (int)g_adjn[i][k];
            float e = es + __ldg(&ed[j]);
            e = (e >= 0.f) ? e : NEG_SLOPE * e;
            p = __expf(e);
        }
        ssum += p;
        const int m = (deg - c0 < 32) ? (deg - c0) : 32;
        int kk = 0;
        for (; kk + 2 <= m; kk += 2) {
            int   ja = __shfl_sync(0xffffffffu, j, kk);
            float pa = __shfl_sync(0xffffffffu, p, kk);
            int   jb = __shfl_sync(0xffffffffu, j, kk + 1);
            float pb = __shfl_sync(0xffffffffu, p, kk + 1);
            float wa = whb[(size_t)ja * OUTF];
            float wb = whb[(size_t)jb * OUTF];
            acc = fmaf(pa, wa, acc);
            acc = fmaf(pb, wb, acc);
        }
        if (kk < m) {
            int   ja = __shfl_sync(0xffffffffu, j, kk);
            float pa = __shfl_sync(0xffffffffu, p, kk);
            acc = fmaf(pa, whb[(size_t)ja * OUTF], acc);
        }
    }
#pragma unroll
    for (int o = 16; o; o >>= 1)
        ssum += __shfl_xor_sync(0xffffffffu, ssum, o);

    out[(size_t)i * (NH * OUTF) + w * OUTF + lane] = acc / ssum + bias[w * OUTF + lane];
}

// ---------------------------------------------------------------------------
extern "C" void kernel_launch(void* const* d_in, const int* in_sizes, int n_in,
                              void* d_out, int out_size) {
    const float* x     = (const float*)d_in[0];
    const void*  adj   = d_in[1];
    const float* W     = (const float*)d_in[2];
    const float* a_src = (const float*)d_in[3];
    const float* a_dst = (const float*)d_in[4];
    const float* bias  = (const float*)d_in[5];
    float*       out   = (float*)d_out;

    gemm_kernel<<<128, 512>>>(x, W, a_src, a_dst, adj);   // writes g_kind (block 0)
    scan_kernel<<<NNODE / 4, 128>>>(adj);                 // reads g_kind
    agg_kernel<<<NNODE, 256>>>(bias, out);
}

// round 14
// speedup vs baseline: 1.1382x; 1.1382x over previous
#include <cuda_runtime.h>
#include <cuda_bf16.h>
#include <cstdint>

#define NNODE 4096
#define INF   256
#define OUTF  32
#define NH    8
#define NEG_SLOPE 0.2f
#define DEGCAP 240

__device__ float          g_Wh[NH * NNODE * OUTF];   // [h][n][f], 4 MB
__device__ float          g_esrc[NH * NNODE];
__device__ float          g_edst[NH * NNODE];
__device__ int            g_deg[NNODE];
__device__ unsigned short g_adjn[NNODE][DEGCAP];
__device__ int            g_kind;                    // 0 = u8, 1 = 32-bit

__device__ __forceinline__ uint32_t smem_u32(const void* p) {
    uint32_t a;
    asm("{ .reg .u64 t; cvta.to.shared.u64 t, %1; cvt.u32.u64 %0, t; }"
        : "=r"(a) : "l"(p));
    return a;
}
#define LDSM4(r0, r1, r2, r3, addr)                                          \
    asm volatile("ldmatrix.sync.aligned.m8n8.x4.shared.b16 {%0,%1,%2,%3}, [%4];" \
                 : "=r"(r0), "=r"(r1), "=r"(r2), "=r"(r3) : "r"(addr))
#define MMA_BF16(c, a, b0, b1)                                               \
    asm volatile("mma.sync.aligned.m16n8k16.row.col.f32.bf16.bf16.f32 "      \
                 "{%0,%1,%2,%3}, {%4,%5,%6,%7}, {%8,%9}, {%0,%1,%2,%3};"     \
                 : "+f"((c)[0]), "+f"((c)[1]), "+f"((c)[2]), "+f"((c)[3])    \
                 : "r"((a)[0]), "r"((a)[1]), "r"((a)[2]), "r"((a)[3]),       \
                   "r"(b0), "r"(b1))

__device__ __forceinline__ uint32_t pack2(float lo, float hi) {
    uint32_t r;
    asm("cvt.rn.bf16x2.f32 %0, %1, %2;" : "=r"(r) : "f"(hi), "f"(lo));
    return r;
}

// smem layout (bytes from base): pitch = 80 B per row (40 bf16)
#define PITCH 80
#define SM_AHI 0
#define SM_ALO 10240
#define SM_BHI 20480
#define SM_BLO 25600

// ---------------------------------------------------------------------------
// gemm_tc: bf16 split-GEMM via mma.sync.  Wh[n, h*32+f] = sum_i x[n,i]*W[h,i,f]
// 128 CTAs x 256 thr; CTA tile 128M x 64N; warp tile 32x32 (one head/warp).
// D += Ahi*Bhi + Ahi*Blo + Alo*Bhi  (fp32 accum; rel err ~1e-5).
// Fused: logit epilogue + adjacency dtype detect (block 0).
// ---------------------------------------------------------------------------
__global__ void __launch_bounds__(256) gemm_tc_kernel(
    const float* __restrict__ x, const float* __restrict__ W,
    const float* __restrict__ a_src, const float* __restrict__ a_dst,
    const void* __restrict__ adjv) {
    __shared__ alignas(128) unsigned char sm[30720];
    __shared__ int s_flag;

    const int t    = threadIdx.x;
    const int bx   = blockIdx.x;
    const int w    = t >> 5;
    const int lane = t & 31;
    const uint32_t base = smem_u32(sm);

    // --- dtype detect (block 0): 16 KB sample, byte pos 1 mod 4
    if (bx == 0) {
        if (t == 0) s_flag = 0;
        __syncthreads();
        unsigned f = 0;
        const uint4* s4 = (const uint4*)adjv;
#pragma unroll
        for (int q = 0; q < 4; q++) {
            uint4 v = s4[t + q * 256];
            f |= ((v.x >> 8) & 0xFFu) | ((v.y >> 8) & 0xFFu)
               | ((v.z >> 8) & 0xFFu) | ((v.w >> 8) & 0xFFu);
        }
#pragma unroll
        for (int o = 16; o; o >>= 1)
            f |= __shfl_xor_sync(0xffffffffu, f, o);
        if (lane == 0 && f) atomicOr(&s_flag, 1);
        __syncthreads();
        if (t == 0) g_kind = s_flag ? 0 : 1;
    }

    const int row0 = (bx >> 2) * 128;   // 32 row tiles
    const int hb   = (bx & 3) * 2;      // heads hb, hb+1
    const int wm   = (w & 3) * 32;      // warp row offset
    const int wn   = (w >> 2) * 32;     // warp col offset (0 or 32)

    float acc[2][4][4];                 // [mf][nf][c0..c3]
#pragma unroll
    for (int a = 0; a < 2; a++)
#pragma unroll
        for (int b = 0; b < 4; b++)
#pragma unroll
            for (int c = 0; c < 4; c++) acc[a][b][c] = 0.f;

    // lane-constant ldmatrix addresses (chunk-invariant parts)
    // A frag (mf, ks): m = wm + mf*16 + ((L>>3)&1)*8 + (L&7), k = ks + (L>>4)*8
    const uint32_t a_m   = (uint32_t)(wm + ((lane >> 3) & 1) * 8 + (lane & 7));
    const uint32_t a_k8  = (uint32_t)((lane >> 4) * 8);
    // B frag (np, ks): n = wn + np*16 + ((L>>4)&1)*8 + (L&7), k = ks + ((L>>3)&1)*8
    const uint32_t b_n   = (uint32_t)(wn + ((lane >> 4) & 1) * 8 + (lane & 7));
    const uint32_t b_k8  = (uint32_t)(((lane >> 3) & 1) * 8);

#pragma unroll 1
    for (int c = 0; c < 8; c++) {
        const int k0 = c * 32;
        // global loads for this chunk (registers; overlap with prior MMA)
        float4 xr[4];
#pragma unroll
        for (int j = 0; j < 4; j++) {
            int idx = t + 256 * j;                        // 0..1023
            xr[j] = *(const float4*)(x + (size_t)(row0 + (idx >> 3)) * INF + k0 + (idx & 7) * 4);
        }
        float wv[8];
#pragma unroll
        for (int j = 0; j < 8; j++) {
            int idx = t + 256 * j;                        // 0..2047
            int n = idx & 63, k = idx >> 6;
            int h = hb + (n >> 5), f = n & 31;
            wv[j] = W[((size_t)h * INF + k0 + k) * OUTF + f];
        }
        if (c > 0) __syncthreads();       // prior MMAs done with smem

        // stage A hi/lo
#pragma unroll
        for (int j = 0; j < 4; j++) {
            int idx = t + 256 * j;
            int row = idx >> 3, kq = idx & 7;
            float4 v = xr[j];
            __nv_bfloat16 h0 = __float2bfloat16(v.x), h1 = __float2bfloat16(v.y);
            __nv_bfloat16 h2 = __float2bfloat16(v.z), h3 = __float2bfloat16(v.w);
            uint2 hp;
            hp.x = pack2(__bfloat162float(h0), __bfloat162float(h1));
            hp.y = pack2(__bfloat162float(h2), __bfloat162float(h3));
            uint2 lp;
            lp.x = pack2(v.x - __bfloat162float(h0), v.y - __bfloat162float(h1));
            lp.y = pack2(v.z - __bfloat162float(h2), v.w - __bfloat162float(h3));
            *(uint2*)(sm + SM_AHI + row * PITCH + kq * 8) = hp;
            *(uint2*)(sm + SM_ALO + row * PITCH + kq * 8) = lp;
        }
        // stage B hi/lo
#pragma unroll
        for (int j = 0; j < 8; j++) {
            int idx = t + 256 * j;
            int n = idx & 63, k = idx >> 6;
            float v = wv[j];
            __nv_bfloat16 h = __float2bfloat16(v);
            float hf = __bfloat162float(h);
            __nv_bfloat16 l = __float2bfloat16(v - hf);
            *(unsigned short*)(sm + SM_BHI + n * PITCH + k * 2) = __bfloat16_as_ushort(h);
            *(unsigned short*)(sm + SM_BLO + n * PITCH + k * 2) = __bfloat16_as_ushort(l);
        }
        __syncthreads();

        // fragments + MMA
#pragma unroll
        for (int ks = 0; ks < 32; ks += 16) {
            uint32_t ah[2][4], al[2][4], bh[4][2], bl[4][2];
#pragma unroll
            for (int mf = 0; mf < 2; mf++) {
                uint32_t addr = base + SM_AHI + (a_m + mf * 16) * PITCH + (ks + a_k8) * 2;
                LDSM4(ah[mf][0], ah[mf][1], ah[mf][2], ah[mf][3], addr);
                LDSM4(al[mf][0], al[mf][1], al[mf][2], al[mf][3], addr + (SM_ALO - SM_AHI));
            }
#pragma unroll
            for (int np = 0; np < 2; np++) {
                uint32_t addr = base + SM_BHI + (b_n + np * 16) * PITCH + (ks + b_k8) * 2;
                uint32_t r0, r1, r2, r3;
                LDSM4(r0, r1, r2, r3, addr);
                bh[np * 2][0] = r0; bh[np * 2][1] = r1;
                bh[np * 2 + 1][0] = r2; bh[np * 2 + 1][1] = r3;
                LDSM4(r0, r1, r2, r3, addr + (SM_BLO - SM_BHI));
                bl[np * 2][0] = r0; bl[np * 2][1] = r1;
                bl[np * 2 + 1][0] = r2; bl[np * 2 + 1][1] = r3;
            }
#pragma unroll
            for (int mf = 0; mf < 2; mf++)
#pragma unroll
                for (int nf = 0; nf < 4; nf++) {
                    MMA_BF16(acc[mf][nf], ah[mf], bh[nf][0], bh[nf][1]);
                    MMA_BF16(acc[mf][nf], ah[mf], bl[nf][0], bl[nf][1]);
                    MMA_BF16(acc[mf][nf], al[mf], bh[nf][0], bh[nf][1]);
                }
        }
    }

    // epilogue: store Wh + fused logits (one head per warp)
    const int h  = hb + (w >> 2);
    const int g  = lane >> 2;
    const int tg = lane & 3;
    float asv[4][2], adv[4][2];
#pragma unroll
    for (int nf = 0; nf < 4; nf++) {
        asv[nf][0] = a_src[h * OUTF + nf * 8 + tg * 2];
        asv[nf][1] = a_src[h * OUTF + nf * 8 + tg * 2 + 1];
        adv[nf][0] = a_dst[h * OUTF + nf * 8 + tg * 2];
        adv[nf][1] = a_dst[h * OUTF + nf * 8 + tg * 2 + 1];
    }
#pragma unroll
    for (int mf = 0; mf < 2; mf++) {
        const int mrow = row0 + wm + mf * 16;
        float s0 = 0.f, d0 = 0.f, s1 = 0.f, d1 = 0.f;
#pragma unroll
        for (int nf = 0; nf < 4; nf++) {
            float c0 = acc[mf][nf][0], c1 = acc[mf][nf][1];
            float c2 = acc[mf][nf][2], c3 = acc[mf][nf][3];
            const int f = nf * 8 + tg * 2;
            float2 vlo; vlo.x = c0; vlo.y = c1;
            float2 vhi; vhi.x = c2; vhi.y = c3;
            *(float2*)(g_Wh + ((size_t)(h << 12) + mrow + g) * OUTF + f)     = vlo;
            *(float2*)(g_Wh + ((size_t)(h << 12) + mrow + 8 + g) * OUTF + f) = vhi;
            s0 += c0 * asv[nf][0] + c1 * asv[nf][1];
            d0 += c0 * adv[nf][0] + c1 * adv[nf][1];
            s1 += c2 * asv[nf][0] + c3 * asv[nf][1];
            d1 += c2 * adv[nf][0] + c3 * adv[nf][1];
        }
#pragma unroll
        for (int o = 1; o < 4; o <<= 1) {
            s0 += __shfl_xor_sync(0xffffffffu, s0, o);
            d0 += __shfl_xor_sync(0xffffffffu, d0, o);
            s1 += __shfl_xor_sync(0xffffffffu, s1, o);
            d1 += __shfl_xor_sync(0xffffffffu, d1, o);
        }
        if (tg == 0) {
            g_esrc[(h << 12) + mrow + g]     = s0;
            g_edst[(h << 12) + mrow + g]     = d0;
            g_esrc[(h << 12) + mrow + 8 + g] = s1;
            g_edst[(h << 12) + mrow + 8 + g] = d1;
        }
    }
}

__device__ __forceinline__ unsigned nib4(unsigned m) {
    return (((m & 0x01010101u) * 0x01020408u) >> 24) & 0xFu;
}

// ---------------------------------------------------------------------------
// scan: 1024 blocks x 128 thr, warp per row, prefetched stream (reads g_kind).
// ---------------------------------------------------------------------------
__global__ void __launch_bounds__(128) scan_kernel(const void* __restrict__ adjv) {
    const int t    = threadIdx.x;
    const int lane = t & 31;
    const int w    = t >> 5;
    const int r    = blockIdx.x * 4 + w;
    const int kind = g_kind;

    int base = 0;
    if (kind == 0) {
        const uint4* rp = (const uint4*)((const unsigned char*)adjv + (size_t)r * NNODE);
        uint4 cur = rp[lane];
        for (int it = 0; it < 8; it++) {
            uint4 nxt;
            if (it < 7) nxt = rp[(it + 1) * 32 + lane];
            unsigned m16 =  nib4(__vcmpne4(cur.x, 0u))
                         | (nib4(__vcmpne4(cur.y, 0u)) << 4)
                         | (nib4(__vcmpne4(cur.z, 0u)) << 8)
                         | (nib4(__vcmpne4(cur.w, 0u)) << 12);
            const int c0 = (it << 9) + (lane << 4);
            if ((unsigned)(r - c0) < 16u) m16 |= 1u << (r - c0);
            int cnt = __popc(m16), incl = cnt;
#pragma unroll
            for (int o = 1; o < 32; o <<= 1) {
                int v = __shfl_up_sync(0xffffffffu, incl, o);
                if (lane >= o) incl += v;
            }
            int pos = base + (incl - cnt);
            int tot = __shfl_sync(0xffffffffu, incl, 31);
            while (m16) {
                int bi = __ffs(m16) - 1;
                m16 &= m16 - 1;
                if (pos < DEGCAP) g_adjn[r][pos] = (unsigned short)(c0 + bi);
                pos++;
            }
            base += tot;
            cur = nxt;
        }
    } else {
        const uint4* rp = (const uint4*)((const unsigned char*)adjv + ((size_t)r * NNODE << 2));
        uint4 cur[4];
#pragma unroll
        for (int q = 0; q < 4; q++) cur[q] = rp[lane * 4 + q];
        for (int it = 0; it < 8; it++) {
            uint4 nxt[4];
            if (it < 7) {
#pragma unroll
                for (int q = 0; q < 4; q++)
                    nxt[q] = rp[(it + 1) * 128 + lane * 4 + q];
            }
            unsigned m16 = 0;
#pragma unroll
            for (int q = 0; q < 4; q++) {
                m16 |= (unsigned)(cur[q].x != 0) << (q * 4 + 0);
                m16 |= (unsigned)(cur[q].y != 0) << (q * 4 + 1);
                m16 |= (unsigned)(cur[q].z != 0) << (q * 4 + 2);
                m16 |= (unsigned)(cur[q].w != 0) << (q * 4 + 3);
            }
            const int c0 = (it << 9) + (lane << 4);
            if ((unsigned)(r - c0) < 16u) m16 |= 1u << (r - c0);
            int cnt = __popc(m16), incl = cnt;
#pragma unroll
            for (int o = 1; o < 32; o <<= 1) {
                int v = __shfl_up_sync(0xffffffffu, incl, o);
                if (lane >= o) incl += v;
            }
            int pos = base + (incl - cnt);
            int tot = __shfl_sync(0xffffffffu, incl, 31);
            while (m16) {
                int bi = __ffs(m16) - 1;
                m16 &= m16 - 1;
                if (pos < DEGCAP) g_adjn[r][pos] = (unsigned short)(c0 + bi);
                pos++;
            }
            base += tot;
#pragma unroll
            for (int q = 0; q < 4; q++) cur[q] = nxt[q];
        }
    }
    if (lane == 31) g_deg[r] = (base > DEGCAP) ? DEGCAP : base;
}

// ---------------------------------------------------------------------------
// agg: warp per (node, head); edge-parallel alpha, shfl-broadcast gather.
// ---------------------------------------------------------------------------
__global__ void __launch_bounds__(256) agg_kernel(
    const float* __restrict__ bias, float* __restrict__ out) {
    const int i    = blockIdx.x;
    const int t    = threadIdx.x;
    const int w    = t >> 5;
    const int lane = t & 31;

    const int    deg = g_deg[i];
    const float  es  = g_esrc[(w << 12) + i];
    const float* ed  = g_edst + (w << 12);
    const float* whb = g_Wh + (((size_t)w << 12) * OUTF) + lane;

    float acc = 0.f, ssum = 0.f;
    for (int c0 = 0; c0 < deg; c0 += 32) {
        const int k = c0 + lane;
        int   j = 0;
        float p = 0.f;
        if (k < deg) {
            j = (int)g_adjn[i][k];
            float e = es + __ldg(&ed[j]);
            e = (e >= 0.f) ? e : NEG_SLOPE * e;
            p = __expf(e);
        }
        ssum += p;
        const int m = (deg - c0 < 32) ? (deg - c0) : 32;
        int kk = 0;
        for (; kk + 2 <= m; kk += 2) {
            int   ja = __shfl_sync(0xffffffffu, j, kk);
            float pa = __shfl_sync(0xffffffffu, p, kk);
            int   jb = __shfl_sync(0xffffffffu, j, kk + 1);
            float pb = __shfl_sync(0xffffffffu, p, kk + 1);
            float wa = whb[(size_t)ja * OUTF];
            float wb = whb[(size_t)jb * OUTF];
            acc = fmaf(pa, wa, acc);
            acc = fmaf(pb, wb, acc);
        }
        if (kk < m) {
            int   ja = __shfl_sync(0xffffffffu, j, kk);
            float pa = __shfl_sync(0xffffffffu, p, kk);
            acc = fmaf(pa, whb[(size_t)ja * OUTF], acc);
        }
    }
#pragma unroll
    for (int o = 16; o; o >>= 1)
        ssum += __shfl_xor_sync(0xffffffffu, ssum, o);

    out[(size_t)i * (NH * OUTF) + w * OUTF + lane] = acc / ssum + bias[w * OUTF + lane];
}

// ---------------------------------------------------------------------------
extern "C" void kernel_launch(void* const* d_in, const int* in_sizes, int n_in,
                              void* d_out, int out_size) {
    const float* x     = (const float*)d_in[0];
    const void*  adj   = d_in[1];
    const float* W     = (const float*)d_in[2];
    const float* a_src = (const float*)d_in[3];
    const float* a_dst = (const float*)d_in[4];
    const float* bias  = (const float*)d_in[5];
    float*       out   = (float*)d_out;

    gemm_tc_kernel<<<128, 256>>>(x, W, a_src, a_dst, adj);  // writes g_kind (block 0)
    scan_kernel<<<NNODE / 4, 128>>>(adj);                   // reads g_kind
    agg_kernel<<<NNODE, 256>>>(bias, out);
}